// round 1
// baseline (speedup 1.0000x reference)
#include <cuda_runtime.h>
#include <math.h>

#define BATCH 4
#define SEQ   2048
#define DIM   1024
#define NH    16
#define HDIM  64
#define MTOT  (BATCH*SEQ)     // 8192
#define NQKV  (3*DIM)         // 3072

// ---------------- scratch (device globals; no allocations allowed) ----------
static __device__ float g_q[(size_t)BATCH*NH*SEQ*HDIM];     // [b*NH+h][s][d]
static __device__ float g_k[(size_t)BATCH*NH*SEQ*HDIM];
static __device__ float g_v[(size_t)BATCH*NH*SEQ*HDIM];
static __device__ float g_attn[(size_t)MTOT*DIM];           // [b*S+s][h*64+d]
static __device__ float g_cos[SEQ*32];
static __device__ float g_sin[SEQ*32];

// ---------------- RoPE cos/sin table ----------------------------------------
__global__ void rope_table_kernel() {
    int idx = blockIdx.x * blockDim.x + threadIdx.x;
    if (idx >= SEQ*32) return;
    int s = idx >> 5;
    int f = idx & 31;
    // inv_freq = 10000^(-2f/64), computed in double for accuracy
    float inv_freq = (float)exp(-((double)(2*f) / 64.0) * log(10000.0));
    float ang = (float)s * inv_freq;
    float sn, cs;
    sincosf(ang, &sn, &cs);
    g_cos[idx] = cs;
    g_sin[idx] = sn;
}

__device__ __forceinline__ void ld4(const float* p, float r[4]) {
    float4 t = *(const float4*)p;
    r[0] = t.x; r[1] = t.y; r[2] = t.z; r[3] = t.w;
}

// ---------------- NT SGEMM: C[M,N] = A[M,K] * B[N,K]^T + bias ----------------
// MODE 0: plain store to C (output projection), A is g_attn
// MODE 1: QKV epilogue: scatter into g_q/g_k/g_v with RoPE applied to q,k
template<int MODE>
__global__ void __launch_bounds__(256)
sgemm_nt(const float* __restrict__ A, const float* __restrict__ Bw,
         const float* __restrict__ bias, float* __restrict__ C,
         int M, int N, int K)
{
    __shared__ float a_s[16][68];   // [k][m], padded stride
    __shared__ float b_s[16][68];   // [k][n]
    __shared__ float c_s[64][64];   // staging for RoPE epilogue (MODE 1)

    const int tid = threadIdx.x;
    const int m0 = blockIdx.y * 64;
    const int n0 = blockIdx.x * 64;
    const int ty = tid >> 4;        // 0..15
    const int tx = tid & 15;        // 0..15
    const int lr = tid >> 2;        // 0..63 row within tile for loading
    const int lc = (tid & 3) * 4;   // 0,4,8,12 within 16-wide k chunk

    const float* Asrc = (MODE == 0) ? (const float*)g_attn : A;
    const float* Ap = Asrc + (size_t)(m0 + lr) * K + lc;
    const float* Bp = Bw   + (size_t)(n0 + lr) * K + lc;

    float acc[4][4] = {};

    for (int k0 = 0; k0 < K; k0 += 16) {
        float4 av = *(const float4*)(Ap + k0);
        float4 bv = *(const float4*)(Bp + k0);
        __syncthreads();
        a_s[lc+0][lr] = av.x; a_s[lc+1][lr] = av.y;
        a_s[lc+2][lr] = av.z; a_s[lc+3][lr] = av.w;
        b_s[lc+0][lr] = bv.x; b_s[lc+1][lr] = bv.y;
        b_s[lc+2][lr] = bv.z; b_s[lc+3][lr] = bv.w;
        __syncthreads();
        #pragma unroll
        for (int k = 0; k < 16; k++) {
            float ar[4], br[4];
            ld4(&a_s[k][ty*4], ar);
            ld4(&b_s[k][tx*4], br);
            #pragma unroll
            for (int i = 0; i < 4; i++)
                #pragma unroll
                for (int j = 0; j < 4; j++)
                    acc[i][j] = fmaf(ar[i], br[j], acc[i][j]);
        }
    }

    if (MODE == 0) {
        float bj[4];
        #pragma unroll
        for (int j = 0; j < 4; j++) bj[j] = bias[n0 + tx*4 + j];
        #pragma unroll
        for (int i = 0; i < 4; i++) {
            int m = m0 + ty*4 + i;
            float4 o;
            o.x = acc[i][0] + bj[0];
            o.y = acc[i][1] + bj[1];
            o.z = acc[i][2] + bj[2];
            o.w = acc[i][3] + bj[3];
            *(float4*)(C + (size_t)m * N + n0 + tx*4) = o;
        }
    } else {
        // stage tile (+bias) in smem, then scatter with RoPE
        float bj[4];
        #pragma unroll
        for (int j = 0; j < 4; j++) bj[j] = bias[n0 + tx*4 + j];
        #pragma unroll
        for (int i = 0; i < 4; i++)
            #pragma unroll
            for (int j = 0; j < 4; j++)
                c_s[ty*4 + i][tx*4 + j] = acc[i][j] + bj[j];
        __syncthreads();

        const int part = n0 >> 10;            // 0=q 1=k 2=v
        const int h    = (n0 & 1023) >> 6;    // head
        const int bb   = m0 / SEQ;            // batch (64 | 2048, no crossing)
        const int s0   = m0 % SEQ;
        const size_t hb = (size_t)(bb * NH + h) * SEQ;

        if (part == 2) {
            #pragma unroll
            for (int r = 0; r < 4; r++) {
                int f4  = tid + r * 256;      // 1024 float4 total
                int row = f4 >> 4;
                int d   = (f4 & 15) * 4;
                float4 v = *(const float4*)&c_s[row][d];
                *(float4*)(g_v + (hb + s0 + row) * HDIM + d) = v;
            }
        } else {
            float* dst = (part == 0) ? g_q : g_k;
            #pragma unroll
            for (int r = 0; r < 8; r++) {
                int p   = tid + r * 256;      // 2048 (row,f) pairs
                int row = p >> 5;
                int f   = p & 31;
                int s   = s0 + row;
                float x1 = c_s[row][f];
                float x2 = c_s[row][f + 32];
                float cv = g_cos[s*32 + f];
                float sv = g_sin[s*32 + f];
                size_t base = (hb + s) * HDIM;
                dst[base + f]      = x1*cv - x2*sv;
                dst[base + f + 32] = x1*sv + x2*cv;
            }
        }
    }
}

// ---------------- Flash attention (fp32), 64x64 tiles -----------------------
// grid: (SEQ/64 q-tiles, BATCH*NH heads), 256 threads
__global__ void __launch_bounds__(256)
attn_kernel()
{
    __shared__ float q_s[64][68];   // [d][qrow], pre-scaled
    __shared__ float k_s[64][68];   // [d][krow]
    __shared__ float v_s[64][68];   // [krow][dv]
    __shared__ float p_s[64][68];   // [krow][qrow]

    const int tid = threadIdx.x;
    const int qt  = blockIdx.x;
    const int bh  = blockIdx.y;
    const size_t hb = (size_t)bh * SEQ * HDIM;

    const float scale = 0.125f;     // 1/sqrt(64)

    #pragma unroll
    for (int r = 0; r < 4; r++) {
        int f4  = tid + r * 256;
        int row = f4 >> 4;
        int d   = (f4 & 15) * 4;
        float4 v = *(const float4*)(g_q + hb + (size_t)(qt*64 + row) * HDIM + d);
        q_s[d+0][row] = v.x * scale; q_s[d+1][row] = v.y * scale;
        q_s[d+2][row] = v.z * scale; q_s[d+3][row] = v.w * scale;
    }

    const int ty = tid >> 4;
    const int tx = tid & 15;
    float acc[4][4] = {};
    float mi[4], li[4];
    #pragma unroll
    for (int i = 0; i < 4; i++) { mi[i] = -1e30f; li[i] = 0.f; }

    for (int kt = 0; kt < SEQ/64; kt++) {
        __syncthreads();    // previous iter done reading k_s/v_s/p_s
        #pragma unroll
        for (int r = 0; r < 4; r++) {
            int f4  = tid + r * 256;
            int row = f4 >> 4;
            int d   = (f4 & 15) * 4;
            size_t off = hb + (size_t)(kt*64 + row) * HDIM + d;
            float4 kv = *(const float4*)(g_k + off);
            k_s[d+0][row] = kv.x; k_s[d+1][row] = kv.y;
            k_s[d+2][row] = kv.z; k_s[d+3][row] = kv.w;
            float4 vv = *(const float4*)(g_v + off);
            *(float4*)&v_s[row][d] = vv;
        }
        __syncthreads();

        // S = Q K^T (pre-scaled)
        float sc[4][4] = {};
        #pragma unroll 8
        for (int d = 0; d < 64; d++) {
            float ar[4], br[4];
            ld4(&q_s[d][ty*4], ar);
            ld4(&k_s[d][tx*4], br);
            #pragma unroll
            for (int i = 0; i < 4; i++)
                #pragma unroll
                for (int j = 0; j < 4; j++)
                    sc[i][j] = fmaf(ar[i], br[j], sc[i][j]);
        }

        // online softmax (row state replicated across tx via shuffles)
        #pragma unroll
        for (int i = 0; i < 4; i++) {
            float rm = fmaxf(fmaxf(sc[i][0], sc[i][1]), fmaxf(sc[i][2], sc[i][3]));
            rm = fmaxf(rm, __shfl_xor_sync(0xffffffffu, rm, 1));
            rm = fmaxf(rm, __shfl_xor_sync(0xffffffffu, rm, 2));
            rm = fmaxf(rm, __shfl_xor_sync(0xffffffffu, rm, 4));
            rm = fmaxf(rm, __shfl_xor_sync(0xffffffffu, rm, 8));
            float mnew  = fmaxf(mi[i], rm);
            float alpha = __expf(mi[i] - mnew);
            float rs = 0.f;
            #pragma unroll
            for (int j = 0; j < 4; j++) {
                float p = __expf(sc[i][j] - mnew);
                sc[i][j] = p;
                rs += p;
            }
            rs += __shfl_xor_sync(0xffffffffu, rs, 1);
            rs += __shfl_xor_sync(0xffffffffu, rs, 2);
            rs += __shfl_xor_sync(0xffffffffu, rs, 4);
            rs += __shfl_xor_sync(0xffffffffu, rs, 8);
            li[i] = li[i] * alpha + rs;
            mi[i] = mnew;
            #pragma unroll
            for (int j = 0; j < 4; j++) acc[i][j] *= alpha;
        }

        // P transposed into smem for the PV GEMM
        #pragma unroll
        for (int i = 0; i < 4; i++)
            #pragma unroll
            for (int j = 0; j < 4; j++)
                p_s[tx*4 + j][ty*4 + i] = sc[i][j];
        __syncthreads();

        // O += P V
        #pragma unroll 8
        for (int j = 0; j < 64; j++) {
            float pr[4], vr[4];
            ld4(&p_s[j][ty*4], pr);
            ld4(&v_s[j][tx*4], vr);
            #pragma unroll
            for (int i = 0; i < 4; i++)
                #pragma unroll
                for (int c = 0; c < 4; c++)
                    acc[i][c] = fmaf(pr[i], vr[c], acc[i][c]);
        }
    }

    // normalize + write to [b*S+s][h*64+dv] layout for the output GEMM
    const int bb = bh >> 4;
    const int h  = bh & 15;
    #pragma unroll
    for (int i = 0; i < 4; i++) {
        float inv = 1.0f / li[i];
        int s = qt*64 + ty*4 + i;
        float4 o;
        o.x = acc[i][0] * inv;
        o.y = acc[i][1] * inv;
        o.z = acc[i][2] * inv;
        o.w = acc[i][3] * inv;
        *(float4*)(g_attn + (size_t)(bb*SEQ + s) * DIM + h*HDIM + tx*4) = o;
    }
}

// ---------------- launcher ---------------------------------------------------
extern "C" void kernel_launch(void* const* d_in, const int* in_sizes, int n_in,
                              void* d_out, int out_size)
{
    const float* hidden = (const float*)d_in[0];
    const float* Wqkv_w = (const float*)d_in[1];
    const float* Wqkv_b = (const float*)d_in[2];
    const float* Wo_w   = (const float*)d_in[3];
    const float* Wo_b   = (const float*)d_in[4];
    float* out = (float*)d_out;

    rope_table_kernel<<<(SEQ*32)/256, 256>>>();

    // QKV GEMM + bias + RoPE scatter: M=8192, N=3072, K=1024
    sgemm_nt<1><<<dim3(NQKV/64, MTOT/64), 256>>>(hidden, Wqkv_w, Wqkv_b,
                                                 nullptr, MTOT, NQKV, DIM);

    // flash attention over 64 heads x 32 q-tiles
    attn_kernel<<<dim3(SEQ/64, BATCH*NH), 256>>>();

    // output projection: M=8192, N=1024, K=1024 (A = g_attn internally)
    sgemm_nt<0><<<dim3(DIM/64, MTOT/64), 256>>>(nullptr, Wo_w, Wo_b,
                                                out, MTOT, DIM, DIM);
}

// round 2
// speedup vs baseline: 2.7848x; 2.7848x over previous
#include <cuda_runtime.h>
#include <math.h>

#define BATCH 4
#define SEQ   2048
#define DIM   1024
#define NH    16
#define HDIM  64
#define MTOT  (BATCH*SEQ)     // 8192
#define NQKV  (3*DIM)         // 3072

// ---------------- scratch (device globals; no allocations allowed) ----------
static __device__ float g_q[(size_t)BATCH*NH*SEQ*HDIM];     // [b*NH+h][s][d]
static __device__ float g_k[(size_t)BATCH*NH*SEQ*HDIM];
static __device__ float g_v[(size_t)BATCH*NH*SEQ*HDIM];
static __device__ float g_attn[(size_t)MTOT*DIM];           // [b*S+s][h*64+d]
static __device__ float g_cos[SEQ*32];
static __device__ float g_sin[SEQ*32];

// ---------------- RoPE cos/sin table ----------------------------------------
__global__ void rope_table_kernel() {
    int idx = blockIdx.x * blockDim.x + threadIdx.x;
    if (idx >= SEQ*32) return;
    int s = idx >> 5;
    int f = idx & 31;
    float inv_freq = (float)exp(-((double)(2*f) / 64.0) * log(10000.0));
    float ang = (float)s * inv_freq;
    float sn, cs;
    sincosf(ang, &sn, &cs);
    g_cos[idx] = cs;
    g_sin[idx] = sn;
}

// ---------------- tf32 helpers ----------------------------------------------
__device__ __forceinline__ unsigned f2tf(float x) {
    unsigned r;
    asm("cvt.rna.tf32.f32 %0, %1;" : "=r"(r) : "f"(x));
    return r;
}

__device__ __forceinline__ void mma8(float c[4],
                                     unsigned a0, unsigned a1, unsigned a2, unsigned a3,
                                     unsigned b0, unsigned b1) {
    asm volatile(
        "mma.sync.aligned.m16n8k8.row.col.f32.tf32.tf32.f32 "
        "{%0,%1,%2,%3},{%4,%5,%6,%7},{%8,%9},{%0,%1,%2,%3};"
        : "+f"(c[0]), "+f"(c[1]), "+f"(c[2]), "+f"(c[3])
        : "r"(a0), "r"(a1), "r"(a2), "r"(a3), "r"(b0), "r"(b1));
}

// ---------------- NT tensor-core GEMM: C[M,N] = A[M,K=1024] * B[N,1024]^T ----
// MODE 0: C = acc + bias (output projection; A = g_attn)
// MODE 1: QKV epilogue: bias + RoPE, scatter into g_q/g_k/g_v
// block: 256 threads (8 warps, 4x2), tile 128x128, warp tile 32x64
template<int MODE>
__global__ void __launch_bounds__(256)
gemm_tc(const float* __restrict__ A, const float* __restrict__ Bw,
        const float* __restrict__ bias, float* __restrict__ C)
{
    __shared__ unsigned a_s[2][128][20];   // [buf][m][k], stride 20 (conflict-free frags)
    __shared__ unsigned b_s[2][128][20];   // [buf][n][k]

    const int tid  = threadIdx.x;
    const int w    = tid >> 5;
    const int lane = tid & 31;
    const int g    = lane >> 2;
    const int t4   = lane & 3;
    const int wm0  = (w >> 1) * 32;
    const int wn0  = (w & 1) * 64;
    const int m0   = blockIdx.y * 128;
    const int n0   = blockIdx.x * 128;

    const int srow = tid >> 2;          // 0..63
    const int scol = (tid & 3) * 4;     // 0,4,8,12

    const float* Ap  = (MODE == 0) ? (const float*)g_attn : A;
    const float* Ag  = Ap + (size_t)(m0 + srow)      * 1024 + scol;
    const float* Ag2 = Ap + (size_t)(m0 + srow + 64) * 1024 + scol;
    const float* Bg  = Bw + (size_t)(n0 + srow)      * 1024 + scol;
    const float* Bg2 = Bw + (size_t)(n0 + srow + 64) * 1024 + scol;

    float4 av0 = *(const float4*)Ag;
    float4 av1 = *(const float4*)Ag2;
    float4 bv0 = *(const float4*)Bg;
    float4 bv1 = *(const float4*)Bg2;

    float acc[2][8][4] = {};

    // initial stage into buffer 0
    *(uint4*)&a_s[0][srow][scol]      = make_uint4(f2tf(av0.x), f2tf(av0.y), f2tf(av0.z), f2tf(av0.w));
    *(uint4*)&a_s[0][srow + 64][scol] = make_uint4(f2tf(av1.x), f2tf(av1.y), f2tf(av1.z), f2tf(av1.w));
    *(uint4*)&b_s[0][srow][scol]      = make_uint4(f2tf(bv0.x), f2tf(bv0.y), f2tf(bv0.z), f2tf(bv0.w));
    *(uint4*)&b_s[0][srow + 64][scol] = make_uint4(f2tf(bv1.x), f2tf(bv1.y), f2tf(bv1.z), f2tf(bv1.w));
    __syncthreads();

    #pragma unroll 1
    for (int it = 0; it < 64; ++it) {
        const int cur = it & 1;
        if (it < 63) {
            const int k0 = (it + 1) * 16;
            av0 = *(const float4*)(Ag  + k0);
            av1 = *(const float4*)(Ag2 + k0);
            bv0 = *(const float4*)(Bg  + k0);
            bv1 = *(const float4*)(Bg2 + k0);
        }
        #pragma unroll
        for (int ks = 0; ks < 2; ++ks) {
            const int kk = ks * 8;
            unsigned af[2][4], bf[8][2];
            #pragma unroll
            for (int mi = 0; mi < 2; ++mi) {
                const int r = wm0 + mi * 16 + g;
                af[mi][0] = a_s[cur][r][kk + t4];
                af[mi][1] = a_s[cur][r + 8][kk + t4];
                af[mi][2] = a_s[cur][r][kk + t4 + 4];
                af[mi][3] = a_s[cur][r + 8][kk + t4 + 4];
            }
            #pragma unroll
            for (int nj = 0; nj < 8; ++nj) {
                const int r = wn0 + nj * 8 + g;
                bf[nj][0] = b_s[cur][r][kk + t4];
                bf[nj][1] = b_s[cur][r][kk + t4 + 4];
            }
            #pragma unroll
            for (int mi = 0; mi < 2; ++mi)
                #pragma unroll
                for (int nj = 0; nj < 8; ++nj)
                    mma8(acc[mi][nj], af[mi][0], af[mi][1], af[mi][2], af[mi][3],
                         bf[nj][0], bf[nj][1]);
        }
        if (it < 63) {
            const int nb = cur ^ 1;
            *(uint4*)&a_s[nb][srow][scol]      = make_uint4(f2tf(av0.x), f2tf(av0.y), f2tf(av0.z), f2tf(av0.w));
            *(uint4*)&a_s[nb][srow + 64][scol] = make_uint4(f2tf(av1.x), f2tf(av1.y), f2tf(av1.z), f2tf(av1.w));
            *(uint4*)&b_s[nb][srow][scol]      = make_uint4(f2tf(bv0.x), f2tf(bv0.y), f2tf(bv0.z), f2tf(bv0.w));
            *(uint4*)&b_s[nb][srow + 64][scol] = make_uint4(f2tf(bv1.x), f2tf(bv1.y), f2tf(bv1.z), f2tf(bv1.w));
        }
        __syncthreads();
    }

    if (MODE == 0) {
        #pragma unroll
        for (int nj = 0; nj < 8; ++nj) {
            const int col = n0 + wn0 + nj * 8 + 2 * t4;
            const float2 bj = *(const float2*)(bias + col);
            #pragma unroll
            for (int mi = 0; mi < 2; ++mi)
                #pragma unroll
                for (int rs = 0; rs < 2; ++rs) {
                    const int m = m0 + wm0 + mi * 16 + g + rs * 8;
                    float2 o;
                    o.x = acc[mi][nj][rs * 2]     + bj.x;
                    o.y = acc[mi][nj][rs * 2 + 1] + bj.y;
                    *(float2*)(C + (size_t)m * 1024 + col) = o;
                }
        }
    } else {
        const int nb   = n0 + wn0;
        const int part = nb >> 10;              // 0=q 1=k 2=v
        const int h    = (nb >> 6) & 15;
        const int bb   = m0 >> 11;              // m0 / 2048
        const int sb   = m0 & 2047;
        float* dst = (part == 0) ? g_q : ((part == 1) ? g_k : g_v);
        const size_t hb = (size_t)(bb * NH + h) * SEQ;

        float2 bj[8];
        #pragma unroll
        for (int j = 0; j < 8; ++j)
            bj[j] = *(const float2*)(bias + nb + j * 8 + 2 * t4);

        if (part == 2) {
            #pragma unroll
            for (int mi = 0; mi < 2; ++mi)
                #pragma unroll
                for (int rs = 0; rs < 2; ++rs) {
                    const int s = sb + wm0 + mi * 16 + g + rs * 8;
                    float* o = dst + (hb + s) * HDIM;
                    #pragma unroll
                    for (int j = 0; j < 8; ++j) {
                        float2 v;
                        v.x = acc[mi][j][rs * 2]     + bj[j].x;
                        v.y = acc[mi][j][rs * 2 + 1] + bj[j].y;
                        *(float2*)(o + j * 8 + 2 * t4) = v;
                    }
                }
        } else {
            #pragma unroll
            for (int mi = 0; mi < 2; ++mi)
                #pragma unroll
                for (int rs = 0; rs < 2; ++rs) {
                    const int s = sb + wm0 + mi * 16 + g + rs * 8;
                    float* o = dst + (hb + s) * HDIM;
                    #pragma unroll
                    for (int j = 0; j < 4; ++j) {
                        const int f = j * 8 + 2 * t4;       // 0..31
                        const float2 cv = *(const float2*)(g_cos + s * 32 + f);
                        const float2 sv = *(const float2*)(g_sin + s * 32 + f);
                        const float x1a = acc[mi][j][rs * 2]         + bj[j].x;
                        const float x1b = acc[mi][j][rs * 2 + 1]     + bj[j].y;
                        const float x2a = acc[mi][j + 4][rs * 2]     + bj[j + 4].x;
                        const float x2b = acc[mi][j + 4][rs * 2 + 1] + bj[j + 4].y;
                        float2 lo, hi;
                        lo.x = x1a * cv.x - x2a * sv.x;
                        lo.y = x1b * cv.y - x2b * sv.y;
                        hi.x = x1a * sv.x + x2a * cv.x;
                        hi.y = x1b * sv.y + x2b * cv.y;
                        *(float2*)(o + f)      = lo;
                        *(float2*)(o + f + 32) = hi;
                    }
                }
        }
    }
}

// ---------------- Flash attention, tf32 tensor cores ------------------------
// block: 128 threads (4 warps), q-tile 128 rows, warp = 32 q-rows
// grid: (SEQ/128, BATCH*NH)
__global__ void __launch_bounds__(128)
attn_tc()
{
    __shared__ unsigned q_s[128][68];   // [q][d] tf32, pre-scaled
    __shared__ unsigned k_s[64][68];    // [kpos][d]
    __shared__ unsigned v_s[64][72];    // [kpos][d]

    const int tid  = threadIdx.x;
    const int w    = tid >> 5;
    const int lane = tid & 31;
    const int g    = lane >> 2;
    const int t4   = lane & 3;
    const int qt   = blockIdx.x;
    const int bh   = blockIdx.y;
    const size_t hb = (size_t)bh * SEQ * HDIM;
    const int wq0  = w * 32;

    // stage Q (scaled by 1/sqrt(64))
    #pragma unroll
    for (int i = 0; i < 16; ++i) {
        const int f   = tid + 128 * i;      // 0..2047
        const int row = f >> 4;
        const int col = (f & 15) * 4;
        float4 v = *(const float4*)(g_q + hb + (size_t)(qt * 128 + row) * HDIM + col);
        *(uint4*)&q_s[row][col] = make_uint4(f2tf(v.x * 0.125f), f2tf(v.y * 0.125f),
                                             f2tf(v.z * 0.125f), f2tf(v.w * 0.125f));
    }

    float O[2][8][4] = {};
    float mi_s[2][2], li[2][2];
    #pragma unroll
    for (int a = 0; a < 2; ++a)
        #pragma unroll
        for (int b = 0; b < 2; ++b) { mi_s[a][b] = -1e30f; li[a][b] = 0.f; }

    const int srow = tid >> 1;          // 0..63
    const int scb  = (tid & 1) * 32;

    #pragma unroll 1
    for (int kt = 0; kt < 32; ++kt) {
        __syncthreads();    // previous tile fully consumed
        // stage K tile
        {
            const float* kg = g_k + hb + (size_t)(kt * 64 + srow) * HDIM + scb;
            float4 tv[8];
            #pragma unroll
            for (int i = 0; i < 8; ++i) tv[i] = *(const float4*)(kg + i * 4);
            #pragma unroll
            for (int i = 0; i < 8; ++i)
                *(uint4*)&k_s[srow][scb + i * 4] =
                    make_uint4(f2tf(tv[i].x), f2tf(tv[i].y), f2tf(tv[i].z), f2tf(tv[i].w));
        }
        // stage V tile
        {
            const float* vg = g_v + hb + (size_t)(kt * 64 + srow) * HDIM + scb;
            float4 tv[8];
            #pragma unroll
            for (int i = 0; i < 8; ++i) tv[i] = *(const float4*)(vg + i * 4);
            #pragma unroll
            for (int i = 0; i < 8; ++i)
                *(uint4*)&v_s[srow][scb + i * 4] =
                    make_uint4(f2tf(tv[i].x), f2tf(tv[i].y), f2tf(tv[i].z), f2tf(tv[i].w));
        }
        __syncthreads();

        // S = Q K^T
        float sc[2][8][4] = {};
        #pragma unroll
        for (int ks = 0; ks < 8; ++ks) {
            const int kk = ks * 8;
            unsigned af[2][4], bf[8][2];
            #pragma unroll
            for (int m2 = 0; m2 < 2; ++m2) {
                const int r = wq0 + m2 * 16 + g;
                af[m2][0] = q_s[r][kk + t4];
                af[m2][1] = q_s[r + 8][kk + t4];
                af[m2][2] = q_s[r][kk + t4 + 4];
                af[m2][3] = q_s[r + 8][kk + t4 + 4];
            }
            #pragma unroll
            for (int nj = 0; nj < 8; ++nj) {
                const int r = nj * 8 + g;
                bf[nj][0] = k_s[r][kk + t4];
                bf[nj][1] = k_s[r][kk + t4 + 4];
            }
            #pragma unroll
            for (int m2 = 0; m2 < 2; ++m2)
                #pragma unroll
                for (int nj = 0; nj < 8; ++nj)
                    mma8(sc[m2][nj], af[m2][0], af[m2][1], af[m2][2], af[m2][3],
                         bf[nj][0], bf[nj][1]);
        }

        // online softmax (rows g, g+8 per m-tile; reduce across quad)
        #pragma unroll
        for (int m2 = 0; m2 < 2; ++m2) {
            #pragma unroll
            for (int rs = 0; rs < 2; ++rs) {
                float mx = -1e30f;
                #pragma unroll
                for (int j = 0; j < 8; ++j) {
                    mx = fmaxf(mx, sc[m2][j][rs * 2]);
                    mx = fmaxf(mx, sc[m2][j][rs * 2 + 1]);
                }
                mx = fmaxf(mx, __shfl_xor_sync(0xffffffffu, mx, 1));
                mx = fmaxf(mx, __shfl_xor_sync(0xffffffffu, mx, 2));
                const float mnew  = fmaxf(mi_s[m2][rs], mx);
                const float alpha = __expf(mi_s[m2][rs] - mnew);
                float sum = 0.f;
                #pragma unroll
                for (int j = 0; j < 8; ++j) {
                    float p0 = __expf(sc[m2][j][rs * 2]     - mnew);
                    float p1 = __expf(sc[m2][j][rs * 2 + 1] - mnew);
                    sum += p0 + p1;
                    sc[m2][j][rs * 2]     = __uint_as_float(f2tf(p0));
                    sc[m2][j][rs * 2 + 1] = __uint_as_float(f2tf(p1));
                }
                sum += __shfl_xor_sync(0xffffffffu, sum, 1);
                sum += __shfl_xor_sync(0xffffffffu, sum, 2);
                li[m2][rs]   = li[m2][rs] * alpha + sum;
                mi_s[m2][rs] = mnew;
                #pragma unroll
                for (int j = 0; j < 8; ++j) {
                    O[m2][j][rs * 2]     *= alpha;
                    O[m2][j][rs * 2 + 1] *= alpha;
                }
            }
        }

        // O += P V  (A-fragments of P gathered from C-fragments via quad shuffles)
        const int srcA = (g << 2) | (t4 >> 1);
        const int srcB = srcA + 2;
        const int esel = t4 & 1;
        #pragma unroll
        for (int ks = 0; ks < 8; ++ks) {
            const int kk = ks * 8;
            unsigned af[2][4], bf[8][2];
            #pragma unroll
            for (int m2 = 0; m2 < 2; ++m2) {
                float lo, hi;
                lo = __shfl_sync(0xffffffffu, sc[m2][ks][0], srcA);
                hi = __shfl_sync(0xffffffffu, sc[m2][ks][1], srcA);
                af[m2][0] = __float_as_uint(esel ? hi : lo);
                lo = __shfl_sync(0xffffffffu, sc[m2][ks][2], srcA);
                hi = __shfl_sync(0xffffffffu, sc[m2][ks][3], srcA);
                af[m2][1] = __float_as_uint(esel ? hi : lo);
                lo = __shfl_sync(0xffffffffu, sc[m2][ks][0], srcB);
                hi = __shfl_sync(0xffffffffu, sc[m2][ks][1], srcB);
                af[m2][2] = __float_as_uint(esel ? hi : lo);
                lo = __shfl_sync(0xffffffffu, sc[m2][ks][2], srcB);
                hi = __shfl_sync(0xffffffffu, sc[m2][ks][3], srcB);
                af[m2][3] = __float_as_uint(esel ? hi : lo);
            }
            #pragma unroll
            for (int nj = 0; nj < 8; ++nj) {
                bf[nj][0] = v_s[kk + t4][nj * 8 + g];
                bf[nj][1] = v_s[kk + t4 + 4][nj * 8 + g];
            }
            #pragma unroll
            for (int m2 = 0; m2 < 2; ++m2)
                #pragma unroll
                for (int nj = 0; nj < 8; ++nj)
                    mma8(O[m2][nj], af[m2][0], af[m2][1], af[m2][2], af[m2][3],
                         bf[nj][0], bf[nj][1]);
        }
    }

    // epilogue: normalize + write [b*S+s][h*64+d]
    const int bb = bh >> 4;
    const int h  = bh & 15;
    #pragma unroll
    for (int m2 = 0; m2 < 2; ++m2)
        #pragma unroll
        for (int rs = 0; rs < 2; ++rs) {
            const float inv = 1.0f / li[m2][rs];
            const int s = qt * 128 + wq0 + m2 * 16 + g + rs * 8;
            float* o = g_attn + (size_t)(bb * SEQ + s) * DIM + h * HDIM;
            #pragma unroll
            for (int j = 0; j < 8; ++j) {
                float2 v;
                v.x = O[m2][j][rs * 2]     * inv;
                v.y = O[m2][j][rs * 2 + 1] * inv;
                *(float2*)(o + j * 8 + 2 * t4) = v;
            }
        }
}

// ---------------- launcher ---------------------------------------------------
extern "C" void kernel_launch(void* const* d_in, const int* in_sizes, int n_in,
                              void* d_out, int out_size)
{
    const float* hidden = (const float*)d_in[0];
    const float* Wqkv_w = (const float*)d_in[1];
    const float* Wqkv_b = (const float*)d_in[2];
    const float* Wo_w   = (const float*)d_in[3];
    const float* Wo_b   = (const float*)d_in[4];
    float* out = (float*)d_out;

    rope_table_kernel<<<(SEQ*32)/256, 256>>>();

    // QKV GEMM + bias + RoPE scatter: M=8192, N=3072, K=1024
    gemm_tc<1><<<dim3(NQKV/128, MTOT/128), 256>>>(hidden, Wqkv_w, Wqkv_b, nullptr);

    // flash attention: 64 heads x 16 q-tiles of 128 rows
    attn_tc<<<dim3(SEQ/128, BATCH*NH), 128>>>();

    // output projection: M=8192, N=1024, K=1024
    gemm_tc<0><<<dim3(DIM/128, MTOT/128), 256>>>(nullptr, Wo_w, Wo_b, out);
}

// round 5
// speedup vs baseline: 10.0481x; 3.6082x over previous
#include <cuda_runtime.h>
#include <cuda_fp16.h>
#include <math.h>
#include <stdint.h>

#define BATCH 4
#define SEQ   2048
#define DIM   1024
#define NH    16
#define HDIM  64
#define MTOT  (BATCH*SEQ)     // 8192
#define NQKV  (3*DIM)         // 3072

// ---------------- scratch (device globals; no allocations allowed) ----------
static __device__ __half g_hid_h[(size_t)MTOT*DIM];
static __device__ __half g_wqkv_h[(size_t)NQKV*DIM];
static __device__ __half g_wo_h[(size_t)DIM*DIM];
static __device__ __half g_qh[(size_t)BATCH*NH*SEQ*HDIM];   // [bh][s][d] (scaled)
static __device__ __half g_kh[(size_t)BATCH*NH*SEQ*HDIM];   // [bh][s][d]
static __device__ __half g_vh[(size_t)BATCH*NH*SEQ*HDIM];   // [bh][s][d]
static __device__ __half g_attn_h[(size_t)MTOT*DIM];        // [b*S+s][h*64+d]
static __device__ float  g_cos[SEQ*32];
static __device__ float  g_sin[SEQ*32];

// scale folded into Q: (1/sqrt(64)) * log2(e)
#define QFAC 0.18033688011112042f

// ---------------- small kernels ----------------------------------------------
__global__ void rope_table_kernel() {
    int idx = blockIdx.x * blockDim.x + threadIdx.x;
    if (idx >= SEQ*32) return;
    int s = idx >> 5;
    int f = idx & 31;
    float inv_freq = (float)exp(-((double)(2*f) / 64.0) * log(10000.0));
    float ang = (float)s * inv_freq;
    float sn, cs;
    sincosf(ang, &sn, &cs);
    g_cos[idx] = cs;
    g_sin[idx] = sn;
}

// fp32 -> fp16 bulk convert into one of the global fp16 buffers
__global__ void f2h_kernel(const float* __restrict__ src, int which, int n4) {
    int i = blockIdx.x * blockDim.x + threadIdx.x;
    if (i >= n4) return;
    __half* dst = (which == 0) ? g_hid_h : (which == 1) ? g_wqkv_h : g_wo_h;
    float4 v = ((const float4*)src)[i];
    __half2 h0 = __floats2half2_rn(v.x, v.y);
    __half2 h1 = __floats2half2_rn(v.z, v.w);
    ((uint2*)dst)[i] = make_uint2(*(uint32_t*)&h0, *(uint32_t*)&h1);
}

// ---------------- asm helpers -------------------------------------------------
__device__ __forceinline__ uint32_t smem_u32(const void* p) {
    uint32_t a;
    asm("{ .reg .u64 t; cvta.to.shared.u64 t, %1; cvt.u32.u64 %0, t; }" : "=r"(a) : "l"(p));
    return a;
}
__device__ __forceinline__ float ex2f(float x) {
    float y;
    asm("ex2.approx.ftz.f32 %0, %1;" : "=f"(y) : "f"(x));
    return y;
}
// pack two floats into f16x2: result = {lo, hi}
__device__ __forceinline__ uint32_t packh2(float hi, float lo) {
    uint32_t r;
    asm("cvt.rn.f16x2.f32 %0, %1, %2;" : "=r"(r) : "f"(hi), "f"(lo));
    return r;
}
__device__ __forceinline__ void mma16816(float c[4], const uint32_t a[4],
                                         uint32_t b0, uint32_t b1) {
    asm volatile(
        "mma.sync.aligned.m16n8k16.row.col.f32.f16.f16.f32 "
        "{%0,%1,%2,%3},{%4,%5,%6,%7},{%8,%9},{%0,%1,%2,%3};"
        : "+f"(c[0]), "+f"(c[1]), "+f"(c[2]), "+f"(c[3])
        : "r"(a[0]), "r"(a[1]), "r"(a[2]), "r"(a[3]), "r"(b0), "r"(b1));
}
__device__ __forceinline__ void ldsm4(uint32_t r[4], uint32_t addr) {
    asm volatile("ldmatrix.sync.aligned.m8n8.x4.shared.b16 {%0,%1,%2,%3}, [%4];"
        : "=r"(r[0]), "=r"(r[1]), "=r"(r[2]), "=r"(r[3]) : "r"(addr));
}
__device__ __forceinline__ void ldsm4t(uint32_t r[4], uint32_t addr) {
    asm volatile("ldmatrix.sync.aligned.m8n8.x4.trans.shared.b16 {%0,%1,%2,%3}, [%4];"
        : "=r"(r[0]), "=r"(r[1]), "=r"(r[2]), "=r"(r[3]) : "r"(addr));
}
__device__ __forceinline__ void cpa16(uint32_t dst, const void* src) {
    asm volatile("cp.async.cg.shared.global [%0], [%1], 16;" :: "r"(dst), "l"(src));
}
#define CP_COMMIT() asm volatile("cp.async.commit_group;" ::: "memory")
template<int N> __device__ __forceinline__ void cp_wait() {
    asm volatile("cp.async.wait_group %0;" :: "n"(N) : "memory");
}

// smem tile: rows of 64 halves (128B), chunk(16B) swizzle: ch ^ (row&7)
__device__ __forceinline__ uint32_t swz(int row, int ch) {
    return (uint32_t)(row * 128 + ((ch ^ (row & 7)) << 4));
}

extern __shared__ char dyn_sm[];

// ---------------- fp16 tensor-core NT GEMM -----------------------------------
// C[M,N] = A[M,1024] * B[N,1024]^T (+bias). Tile 128x128, 8 warps (4m x 2n),
// warp tile 32x64, k-stage 64. MODE 0: proj (A=g_attn_h, fp32 out).
// MODE 1: QKV (A=g_hid_h), epilogue: bias + RoPE, fp16 scatter to g_qh/g_kh/g_vh.
// smem: A bufs @0/16384, B bufs @32768/49152 (16KB each) = 64KB dynamic.
template<int MODE>
__global__ void __launch_bounds__(256, 2)
gemm_h(const float* __restrict__ bias, float* __restrict__ C)
{
    const __half* Ah = (MODE == 1) ? g_hid_h : g_attn_h;
    const __half* Bh = (MODE == 1) ? g_wqkv_h : g_wo_h;

    const uint32_t sb = smem_u32(dyn_sm);
    const int tid  = threadIdx.x;
    const int w    = tid >> 5;
    const int lane = tid & 31;
    const int g    = lane >> 2;
    const int t4   = lane & 3;
    const int wm0  = (w >> 1) * 32;
    const int wn0  = (w & 1) * 64;
    const int m0   = blockIdx.y * 128;
    const int n0   = blockIdx.x * 128;

    const int crow = tid >> 3;          // 0..31 (staging base row)
    const int cch  = tid & 7;

    // ldmatrix lane patterns
    const int lrA = (lane & 7) + ((lane >> 3) & 1) * 8;   // A / V-trans row
    const int lhA = lane >> 4;                            // A chunk hi
    const int lrB = (lane & 7) + ((lane >> 4) & 1) * 8;   // B row
    const int lhB = (lane >> 3) & 1;                      // B chunk hi

    float acc[2][8][4] = {};

    {   // prologue: stage k0=0 into buf 0
        #pragma unroll
        for (int r = 0; r < 4; ++r) {
            int row = crow + 32 * r;
            cpa16(sb + swz(row, cch),          Ah + (size_t)(m0 + row) * 1024 + cch * 8);
            cpa16(sb + 32768u + swz(row, cch), Bh + (size_t)(n0 + row) * 1024 + cch * 8);
        }
        CP_COMMIT();
    }

    #pragma unroll 1
    for (int it = 0; it < 16; ++it) {
        const int buf = it & 1;
        if (it < 15) {
            const int k0 = (it + 1) * 64;
            const uint32_t bo = (uint32_t)(buf ^ 1) * 16384u;
            #pragma unroll
            for (int r = 0; r < 4; ++r) {
                int row = crow + 32 * r;
                cpa16(sb + bo + swz(row, cch),
                      Ah + (size_t)(m0 + row) * 1024 + k0 + cch * 8);
                cpa16(sb + 32768u + bo + swz(row, cch),
                      Bh + (size_t)(n0 + row) * 1024 + k0 + cch * 8);
            }
            CP_COMMIT();
            cp_wait<1>();
        } else {
            cp_wait<0>();
        }
        __syncthreads();

        const uint32_t Ab = sb + (uint32_t)buf * 16384u;
        const uint32_t Bb = sb + 32768u + (uint32_t)buf * 16384u;
        #pragma unroll
        for (int kc = 0; kc < 4; ++kc) {
            uint32_t a[2][4];
            #pragma unroll
            for (int mi = 0; mi < 2; ++mi)
                ldsm4(a[mi], Ab + swz(wm0 + mi * 16 + lrA, kc * 2 + lhA));
            #pragma unroll
            for (int np = 0; np < 4; ++np) {
                uint32_t b4[4];
                ldsm4(b4, Bb + swz(wn0 + np * 16 + lrB, kc * 2 + lhB));
                #pragma unroll
                for (int mi = 0; mi < 2; ++mi) {
                    mma16816(acc[mi][2 * np],     a[mi], b4[0], b4[1]);
                    mma16816(acc[mi][2 * np + 1], a[mi], b4[2], b4[3]);
                }
            }
        }
        __syncthreads();
    }

    // ---- epilogues ----
    if (MODE == 0) {
        #pragma unroll
        for (int nj = 0; nj < 8; ++nj) {
            const int col = n0 + wn0 + nj * 8 + 2 * t4;
            const float2 bj = *(const float2*)(bias + col);
            #pragma unroll
            for (int mi = 0; mi < 2; ++mi)
                #pragma unroll
                for (int rs = 0; rs < 2; ++rs) {
                    const int m = m0 + wm0 + mi * 16 + g + rs * 8;
                    float2 o;
                    o.x = acc[mi][nj][rs * 2]     + bj.x;
                    o.y = acc[mi][nj][rs * 2 + 1] + bj.y;
                    *(float2*)(C + (size_t)m * 1024 + col) = o;
                }
        }
    } else {
        const int nb   = n0 + wn0;
        const int part = nb >> 10;              // 0=q 1=k 2=v
        const int h    = (nb >> 6) & 15;
        const int bb   = m0 >> 11;
        const int sbq  = m0 & 2047;
        const size_t hb = (size_t)(bb * NH + h) * SEQ;

        float2 bj[8];
        #pragma unroll
        for (int j = 0; j < 8; ++j)
            bj[j] = *(const float2*)(bias + nb + j * 8 + 2 * t4);

        if (part == 2) {
            #pragma unroll
            for (int mi = 0; mi < 2; ++mi)
                #pragma unroll
                for (int rs = 0; rs < 2; ++rs) {
                    const int s = sbq + wm0 + mi * 16 + g + rs * 8;
                    __half* o = g_vh + (hb + s) * HDIM;
                    #pragma unroll
                    for (int j = 0; j < 8; ++j) {
                        uint32_t p = packh2(acc[mi][j][rs * 2 + 1] + bj[j].y,
                                            acc[mi][j][rs * 2]     + bj[j].x);
                        *(uint32_t*)(o + j * 8 + 2 * t4) = p;
                    }
                }
        } else {
            __half* dst = (part == 0) ? g_qh : g_kh;
            const float fac = (part == 0) ? QFAC : 1.0f;
            #pragma unroll
            for (int mi = 0; mi < 2; ++mi)
                #pragma unroll
                for (int rs = 0; rs < 2; ++rs) {
                    const int s = sbq + wm0 + mi * 16 + g + rs * 8;
                    __half* o = dst + (hb + s) * HDIM;
                    #pragma unroll
                    for (int j = 0; j < 4; ++j) {
                        const int f = j * 8 + 2 * t4;       // 0..31
                        const float2 cv = *(const float2*)(g_cos + s * 32 + f);
                        const float2 sv = *(const float2*)(g_sin + s * 32 + f);
                        const float x1a = acc[mi][j][rs * 2]         + bj[j].x;
                        const float x1b = acc[mi][j][rs * 2 + 1]     + bj[j].y;
                        const float x2a = acc[mi][j + 4][rs * 2]     + bj[j + 4].x;
                        const float x2b = acc[mi][j + 4][rs * 2 + 1] + bj[j + 4].y;
                        uint32_t lo = packh2((x1b * cv.y - x2b * sv.y) * fac,
                                             (x1a * cv.x - x2a * sv.x) * fac);
                        uint32_t hi = packh2((x1b * sv.y + x2b * cv.y) * fac,
                                             (x1a * sv.x + x2a * cv.x) * fac);
                        *(uint32_t*)(o + f)      = lo;
                        *(uint32_t*)(o + f + 32) = hi;
                    }
                }
        }
    }
}

// ---------------- fp16 flash attention ---------------------------------------
// block 128 threads (4 warps), q-tile 128 rows, warp = 32 q-rows.
// smem: Q @0 (16KB), K bufs @16384+b*8192, V bufs @32768+b*8192 = 48KB.
// grid (SEQ/128, BATCH*NH)
__global__ void __launch_bounds__(128, 2)
attn_h()
{
    const uint32_t sb = smem_u32(dyn_sm);
    const int tid  = threadIdx.x;
    const int w    = tid >> 5;
    const int lane = tid & 31;
    const int g    = lane >> 2;
    const int t4   = lane & 3;
    const int qt   = blockIdx.x;
    const int bh   = blockIdx.y;
    const size_t hb = (size_t)bh * SEQ * HDIM;
    const int wq0  = w * 32;

    const int crow = tid >> 3;          // 0..15 staging base row
    const int cch  = tid & 7;

    const int lrA = (lane & 7) + ((lane >> 3) & 1) * 8;
    const int lhA = lane >> 4;
    const int lrB = (lane & 7) + ((lane >> 4) & 1) * 8;
    const int lhB = (lane >> 3) & 1;

    // prologue: stage Q (8 chunks/thread) + K0,V0, one group
    {
        const __half* qsrc = g_qh + hb + (size_t)qt * 128 * HDIM;
        #pragma unroll
        for (int r = 0; r < 8; ++r) {
            int row = crow + 16 * r;
            cpa16(sb + swz(row, cch), qsrc + row * HDIM + cch * 8);
        }
        const __half* ksrc = g_kh + hb;
        const __half* vsrc = g_vh + hb;
        #pragma unroll
        for (int r = 0; r < 4; ++r) {
            int row = crow + 16 * r;
            cpa16(sb + 16384u + swz(row, cch), ksrc + row * HDIM + cch * 8);
            cpa16(sb + 32768u + swz(row, cch), vsrc + row * HDIM + cch * 8);
        }
        CP_COMMIT();
    }

    float O[2][8][4] = {};
    float mi_s[2][2], li[2][2];
    #pragma unroll
    for (int a = 0; a < 2; ++a)
        #pragma unroll
        for (int b = 0; b < 2; ++b) { mi_s[a][b] = -1e30f; li[a][b] = 0.f; }

    uint32_t qf[2][4][4];   // Q A-frags, preloaded once

    #pragma unroll 1
    for (int kt = 0; kt < 32; ++kt) {
        const int buf = kt & 1;
        if (kt < 31) {
            const uint32_t bo = (uint32_t)(buf ^ 1) * 8192u;
            const __half* ksrc = g_kh + hb + (size_t)(kt + 1) * 64 * HDIM;
            const __half* vsrc = g_vh + hb + (size_t)(kt + 1) * 64 * HDIM;
            #pragma unroll
            for (int r = 0; r < 4; ++r) {
                int row = crow + 16 * r;
                cpa16(sb + 16384u + bo + swz(row, cch), ksrc + row * HDIM + cch * 8);
                cpa16(sb + 32768u + bo + swz(row, cch), vsrc + row * HDIM + cch * 8);
            }
            CP_COMMIT();
            cp_wait<1>();
        } else {
            cp_wait<0>();
        }
        __syncthreads();

        if (kt == 0) {
            #pragma unroll
            for (int mi = 0; mi < 2; ++mi)
                #pragma unroll
                for (int kc = 0; kc < 4; ++kc)
                    ldsm4(qf[mi][kc], sb + swz(wq0 + mi * 16 + lrA, kc * 2 + lhA));
        }

        // ---- S = Q K^T ----
        const uint32_t Kb = sb + 16384u + (uint32_t)buf * 8192u;
        float sc[2][8][4] = {};
        #pragma unroll
        for (int kc = 0; kc < 4; ++kc) {
            #pragma unroll
            for (int np = 0; np < 4; ++np) {
                uint32_t b4[4];
                ldsm4(b4, Kb + swz(np * 16 + lrB, kc * 2 + lhB));
                #pragma unroll
                for (int mi = 0; mi < 2; ++mi) {
                    mma16816(sc[mi][2 * np],     qf[mi][kc], b4[0], b4[1]);
                    mma16816(sc[mi][2 * np + 1], qf[mi][kc], b4[2], b4[3]);
                }
            }
        }

        // ---- online softmax (base-2 domain; scale folded into Q) ----
        #pragma unroll
        for (int mi = 0; mi < 2; ++mi) {
            #pragma unroll
            for (int rs = 0; rs < 2; ++rs) {
                float mx = -1e30f;
                #pragma unroll
                for (int j = 0; j < 8; ++j) {
                    mx = fmaxf(mx, sc[mi][j][rs * 2]);
                    mx = fmaxf(mx, sc[mi][j][rs * 2 + 1]);
                }
                mx = fmaxf(mx, __shfl_xor_sync(0xffffffffu, mx, 1));
                mx = fmaxf(mx, __shfl_xor_sync(0xffffffffu, mx, 2));
                const float mnew  = fmaxf(mi_s[mi][rs], mx);
                const float alpha = ex2f(mi_s[mi][rs] - mnew);
                float sum = 0.f;
                #pragma unroll
                for (int j = 0; j < 8; ++j) {
                    float p0 = ex2f(sc[mi][j][rs * 2]     - mnew);
                    float p1 = ex2f(sc[mi][j][rs * 2 + 1] - mnew);
                    sum += p0 + p1;
                    sc[mi][j][rs * 2]     = p0;
                    sc[mi][j][rs * 2 + 1] = p1;
                }
                sum += __shfl_xor_sync(0xffffffffu, sum, 1);
                sum += __shfl_xor_sync(0xffffffffu, sum, 2);
                li[mi][rs]   = li[mi][rs] * alpha + sum;
                mi_s[mi][rs] = mnew;
                #pragma unroll
                for (int j = 0; j < 8; ++j) {
                    O[mi][j][rs * 2]     *= alpha;
                    O[mi][j][rs * 2 + 1] *= alpha;
                }
            }
        }

        // ---- O += P V (P A-frags via register repack; V via ldmatrix.trans) --
        const uint32_t Vb = sb + 32768u + (uint32_t)buf * 8192u;
        #pragma unroll
        for (int kc = 0; kc < 4; ++kc) {
            uint32_t pa[2][4];
            #pragma unroll
            for (int mi = 0; mi < 2; ++mi) {
                pa[mi][0] = packh2(sc[mi][2 * kc][1],     sc[mi][2 * kc][0]);
                pa[mi][1] = packh2(sc[mi][2 * kc][3],     sc[mi][2 * kc][2]);
                pa[mi][2] = packh2(sc[mi][2 * kc + 1][1], sc[mi][2 * kc + 1][0]);
                pa[mi][3] = packh2(sc[mi][2 * kc + 1][3], sc[mi][2 * kc + 1][2]);
            }
            #pragma unroll
            for (int np = 0; np < 4; ++np) {
                uint32_t v4[4];
                ldsm4t(v4, Vb + swz(kc * 16 + lrA, np * 2 + lhA));
                #pragma unroll
                for (int mi = 0; mi < 2; ++mi) {
                    mma16816(O[mi][2 * np],     pa[mi], v4[0], v4[1]);
                    mma16816(O[mi][2 * np + 1], pa[mi], v4[2], v4[3]);
                }
            }
        }
        __syncthreads();
    }

    // ---- epilogue: O/l -> fp16 -> g_attn_h [b*S+s][h*64+d] ----
    const int bb = bh >> 4;
    const int h  = bh & 15;
    #pragma unroll
    for (int mi = 0; mi < 2; ++mi)
        #pragma unroll
        for (int rs = 0; rs < 2; ++rs) {
            const float inv = 1.0f / li[mi][rs];
            const int s = qt * 128 + wq0 + mi * 16 + g + rs * 8;
            __half* o = g_attn_h + (size_t)(bb * SEQ + s) * DIM + h * HDIM;
            #pragma unroll
            for (int j = 0; j < 8; ++j) {
                uint32_t p = packh2(O[mi][j][rs * 2 + 1] * inv,
                                    O[mi][j][rs * 2]     * inv);
                *(uint32_t*)(o + j * 8 + 2 * t4) = p;
            }
        }
}

// ---------------- launcher ----------------------------------------------------
extern "C" void kernel_launch(void* const* d_in, const int* in_sizes, int n_in,
                              void* d_out, int out_size)
{
    const float* hidden = (const float*)d_in[0];
    const float* Wqkv_w = (const float*)d_in[1];
    const float* Wqkv_b = (const float*)d_in[2];
    const float* Wo_w   = (const float*)d_in[3];
    const float* Wo_b   = (const float*)d_in[4];
    float* out = (float*)d_out;

    static int attr_done = 0;
    if (!attr_done) {
        cudaFuncSetAttribute(gemm_h<0>, cudaFuncAttributeMaxDynamicSharedMemorySize, 65536);
        cudaFuncSetAttribute(gemm_h<1>, cudaFuncAttributeMaxDynamicSharedMemorySize, 65536);
        cudaFuncSetAttribute(attn_h,    cudaFuncAttributeMaxDynamicSharedMemorySize, 49152);
        attr_done = 1;
    }

    rope_table_kernel<<<(SEQ*32)/256, 256>>>();
    f2h_kernel<<<(MTOT*DIM/4 + 255)/256, 256>>>(hidden, 0, MTOT*DIM/4);
    f2h_kernel<<<(NQKV*DIM/4 + 255)/256, 256>>>(Wqkv_w, 1, NQKV*DIM/4);
    f2h_kernel<<<(DIM*DIM/4 + 255)/256, 256>>>(Wo_w, 2, DIM*DIM/4);

    // QKV GEMM + bias + RoPE scatter (fp16 out)
    gemm_h<1><<<dim3(NQKV/128, MTOT/128), 256, 65536>>>(Wqkv_b, nullptr);

    // flash attention: 64 heads x 16 q-tiles of 128 rows
    attn_h<<<dim3(SEQ/128, BATCH*NH), 128, 49152>>>();

    // output projection (fp32 out)
    gemm_h<0><<<dim3(DIM/128, MTOT/128), 256, 65536>>>(Wo_b, out);
}